// round 2
// baseline (speedup 1.0000x reference)
#include <cuda_runtime.h>
#include <cstdint>
#include <cstddef>

#define DD     256
#define LL     3
#define NSEQ   6300
#define TSq    5400
#define BBn    16
#define MROWS  (BBn*NSEQ)
#define FBROWS (BBn*900)
#define DSLOT  145
#define INV_SQRT_DC 0.08838834764831843f

// ---------------- scratch (device globals) ----------------
__device__ float g_cur [(size_t)MROWS*DD];
__device__ float g_h   [(size_t)MROWS*DD];
__device__ float g_q   [(size_t)MROWS*128];
__device__ float g_sc  [(size_t)MROWS*64];
__device__ float g_qf  [(size_t)MROWS*DD];
__device__ float g_att [(size_t)MROWS*DD];
__device__ float g_qkv [(size_t)MROWS*768];
__device__ float g_cache[BBn*48*DSLOT];
__device__ float g_kc  [BBn*128*64];     // k^T padded to 64 slots
__device__ float g_vc  [BBn*48*256];
__device__ float g_kv  [64*4096];
__device__ float g_ks  [64*64];
__device__ float g_kvp [16*64*4096];
__device__ float g_ksp [16*64*64];
__device__ float g_wk  [BBn*64*128];
__device__ float g_wv  [BBn*64*128];
__device__ float g_cos [NSEQ*32];
__device__ float g_sin [NSEQ*32];
__device__ float g_logits[FBROWS*16];
__device__ float g_fbin [(size_t)FBROWS*512];
__device__ float g_fbout[(size_t)FBROWS*256];

__device__ __forceinline__ float sigm(float x){ return 1.f/(1.f+expf(-x)); }
__device__ __forceinline__ float elu1(float x){ return x>0.f ? x+1.f : expf(x); }

// ---------------- init ----------------
__global__ void k_rope(){
    int i = blockIdx.x*256 + threadIdx.x;
    if (i >= NSEQ*32) return;
    int n = i/32, j = i%32;
    float inv = 1.f/powf(10000.f, (float)(2*j)/64.f);
    float f = (float)n * inv;
    g_cos[i] = cosf(f);
    g_sin[i] = sinf(f);
}

__global__ void k_embed(const int* __restrict__ di, const int* __restrict__ dou,
                        const int* __restrict__ ti, const float* __restrict__ tok,
                        const float* __restrict__ seg){
    int n = blockIdx.x, b = blockIdx.y, t = threadIdx.x;
    int tk;
    if (n < TSq){
        int d = n/1800, rem = n%1800, w = rem/900, s = rem%900;
        tk = w ? dou[(b*3+d)*900+s] : di[(b*3+d)*900+s];
    } else {
        tk = ti[b*900 + (n-TSq)];
    }
    g_cur[((size_t)b*NSEQ+n)*DD + t] = tok[tk*DD+t] + seg[t];
}

__global__ void k_cache_init(const float* __restrict__ se, const float* __restrict__ lid){
    int i = blockIdx.x*256 + threadIdx.x;
    if (i >= BBn*48*DSLOT) return;
    int r2 = i % (48*DSLOT);
    int slot = r2 / DSLOT, c = r2 % DSLOT;
    float v = 0.f;
    if (c < 128)                  v = se[slot*128 + c];
    else if (c >= 129 && c < 137) v = lid[(slot/16)*8 + (c-129)];
    g_cache[i] = v;
}

__global__ void k_copy(){
    size_t i = (size_t)blockIdx.x*256 + threadIdx.x;
    ((float4*)g_h)[i] = ((const float4*)g_cur)[i];
}

// ---------------- generic tiled GEMM ----------------
// C[M,N] (+)= A[M,K] @ B[K,N]; 64x64 tile, BK=16, 256 thr, 4x4/thr.
// batching: bz = blockIdx.z; b1=bz/bdiv, b2=bz%bdiv; strides sX1/sX2.
// Requires: N % 64 == 0, K % 16 == 0, pointers/ld 16B-aligned.
__global__ void __launch_bounds__(256) k_gemm(
    const float* __restrict__ A, const float* __restrict__ B, float* __restrict__ C,
    int M, int N, int K, int lda, int ldb, int ldc,
    int bdiv, long sA1, long sA2, long sB1, long sB2, long sC1, long sC2, int doAdd)
{
    __shared__ float As[64][17];
    __shared__ float Bs[16][64];
    int bz = blockIdx.z;
    int b1 = bz / bdiv, b2 = bz % bdiv;
    A += (size_t)b1*sA1 + (size_t)b2*sA2;
    B += (size_t)b1*sB1 + (size_t)b2*sB2;
    C += (size_t)b1*sC1 + (size_t)b2*sC2;
    const int t  = threadIdx.x;
    const int tx = t & 15, ty = t >> 4;
    const int arow = t >> 2, acol = (t & 3) << 2;
    const int brow = t >> 4, bcol = (t & 15) << 2;
    const int grow = blockIdx.y*64 + arow;
    const bool aok = grow < M;
    const float* Ap = A + (size_t)grow*lda + acol;
    const float* Bp = B + (size_t)brow*ldb + blockIdx.x*64 + bcol;
    float acc[4][4];
    #pragma unroll
    for (int i=0;i<4;i++){
        #pragma unroll
        for (int j=0;j<4;j++) acc[i][j]=0.f;
    }
    for (int k0=0; k0<K; k0+=16){
        float4 av = make_float4(0.f,0.f,0.f,0.f);
        if (aok) av = *(const float4*)(Ap + k0);
        float4 bv = *(const float4*)(Bp + (size_t)k0*ldb);
        As[arow][acol+0]=av.x; As[arow][acol+1]=av.y;
        As[arow][acol+2]=av.z; As[arow][acol+3]=av.w;
        *(float4*)&Bs[brow][bcol] = bv;
        __syncthreads();
        #pragma unroll
        for (int kk=0; kk<16; kk++){
            float4 bq = *(const float4*)&Bs[kk][tx<<2];
            float a0=As[(ty<<2)+0][kk], a1=As[(ty<<2)+1][kk];
            float a2=As[(ty<<2)+2][kk], a3=As[(ty<<2)+3][kk];
            acc[0][0]+=a0*bq.x; acc[0][1]+=a0*bq.y; acc[0][2]+=a0*bq.z; acc[0][3]+=a0*bq.w;
            acc[1][0]+=a1*bq.x; acc[1][1]+=a1*bq.y; acc[1][2]+=a1*bq.z; acc[1][3]+=a1*bq.w;
            acc[2][0]+=a2*bq.x; acc[2][1]+=a2*bq.y; acc[2][2]+=a2*bq.z; acc[2][3]+=a2*bq.w;
            acc[3][0]+=a3*bq.x; acc[3][1]+=a3*bq.y; acc[3][2]+=a3*bq.z; acc[3][3]+=a3*bq.w;
        }
        __syncthreads();
    }
    #pragma unroll
    for (int i=0;i<4;i++){
        int row = blockIdx.y*64 + (ty<<2) + i;
        if (row >= M) continue;
        float* cp = C + (size_t)row*ldc + blockIdx.x*64 + (tx<<2);
        if (doAdd){
            float4 c0 = *(float4*)cp;
            c0.x+=acc[i][0]; c0.y+=acc[i][1]; c0.z+=acc[i][2]; c0.w+=acc[i][3];
            *(float4*)cp = c0;
        } else {
            *(float4*)cp = make_float4(acc[i][0],acc[i][1],acc[i][2],acc[i][3]);
        }
    }
}

// ---------------- cache k,v projections (k transposed + padded) ----------------
__global__ void k_cachekv(const float* __restrict__ Wk, const float* __restrict__ Wv){
    int idx = blockIdx.x*256 + threadIdx.x;          // 16 * 20480
    if (idx >= BBn*20480) return;
    int b = idx / 20480, o = idx % 20480;
    const float* cb = g_cache + (size_t)b*48*DSLOT;
    if (o < 8192){
        int d = o >> 6, m = o & 63;
        float a = 0.f;
        if (m < 48){
            const float* row = cb + (size_t)m*DSLOT;
            for (int dd=0; dd<DSLOT; dd++) a += row[dd]*Wk[dd*128 + d];
        }
        g_kc[b*8192 + d*64 + m] = a;
    } else {
        int o2 = o - 8192;
        int m = o2 >> 8, j = o2 & 255;
        const float* row = cb + (size_t)m*DSLOT;
        float a = 0.f;
        for (int dd=0; dd<DSLOT; dd++) a += row[dd]*Wv[dd*256 + j];
        g_vc[b*12288 + o2] = a;
    }
}

// ---------------- softmax over 48 slots + fold rgate into weights ----------------
__global__ void k_softrg(const float* __restrict__ Wg, const float* __restrict__ bg, int l){
    int gw = blockIdx.x*8 + (threadIdx.x>>5);
    int lane = threadIdx.x & 31;
    if (gw >= MROWS) return;
    const float* hrow = g_h + (size_t)gw*256;
    const float* wg = Wg + l*256;
    float pg = 0.f;
    #pragma unroll
    for (int j=0;j<8;j++) pg += hrow[lane + 32*j]*wg[lane + 32*j];
    #pragma unroll
    for (int o=16;o;o>>=1) pg += __shfl_xor_sync(0xffffffffu, pg, o);
    float rgate = sigm(pg + bg[l]);
    float* scp = g_sc + (size_t)gw*64;
    float s0 = scp[lane]*INV_SQRT_DC;
    float s1 = (lane<16) ? scp[lane+32]*INV_SQRT_DC : -1e30f;
    float mx = fmaxf(s0, s1);
    #pragma unroll
    for (int o=16;o;o>>=1) mx = fmaxf(mx, __shfl_xor_sync(0xffffffffu, mx, o));
    float e0 = expf(s0-mx);
    float e1 = (lane<16) ? expf(s1-mx) : 0.f;
    float su = e0+e1;
    #pragma unroll
    for (int o=16;o;o>>=1) su += __shfl_xor_sync(0xffffffffu, su, o);
    float sc = rgate/su;
    scp[lane] = e0*sc;
    if (lane<16) scp[lane+32] = e1*sc;
}

// ---------------- linear attention: kv / ksum partials ----------------
__global__ void __launch_bounds__(256) k_kvacc(){
    int bh = blockIdx.y;
    int b = bh >> 2, h = bh & 3;
    int n0 = blockIdx.x*396;
    __shared__ float kf[4*64];
    __shared__ float vh[4*64];
    int t = threadIdx.x;
    int d = t >> 2, eb = (t & 3) << 4;
    float acc[16];
    #pragma unroll
    for (int j=0;j<16;j++) acc[j]=0.f;
    float ksa = 0.f;
    for (int nb=0; nb<396; nb+=4){
        int nbase = n0 + nb;
        if (t < 128){
            int sub = t>>5, i2 = t&31;
            int n = nbase + sub;
            float v1=0.f, v2=0.f;
            if (n < NSEQ){
                const float* bp = g_qkv + (size_t)(b*NSEQ+n)*768 + 256 + h*64;
                float x1=bp[2*i2], x2=bp[2*i2+1];
                float c=g_cos[n*32+i2], s=g_sin[n*32+i2];
                v1 = elu1(x1*c - x2*s);
                v2 = elu1(x1*s + x2*c);
            }
            kf[sub*64+2*i2]=v1; kf[sub*64+2*i2+1]=v2;
        } else {
            int t2 = t-128;
            #pragma unroll
            for (int q2=0;q2<2;q2++){
                int idx = t2 + q2*128;
                int sub = idx>>6, j = idx&63;
                int n = nbase + sub;
                vh[sub*64+j] = (n<NSEQ) ? g_qkv[(size_t)(b*NSEQ+n)*768 + 512 + h*64 + j] : 0.f;
            }
        }
        __syncthreads();
        #pragma unroll
        for (int sub=0; sub<4; sub++){
            float kd = kf[sub*64+d];
            ksa += kd;
            const float4* vp = (const float4*)&vh[sub*64+eb];
            #pragma unroll
            for (int q4=0;q4<4;q4++){
                float4 v4 = vp[q4];
                acc[q4*4+0]+=kd*v4.x; acc[q4*4+1]+=kd*v4.y;
                acc[q4*4+2]+=kd*v4.z; acc[q4*4+3]+=kd*v4.w;
            }
        }
        __syncthreads();
    }
    float* kvp = g_kvp + ((size_t)(blockIdx.x*64+bh))*4096 + d*64 + eb;
    #pragma unroll
    for (int j=0;j<16;j++) kvp[j] = acc[j];
    if ((t&3)==0) g_ksp[(blockIdx.x*64+bh)*64 + d] = ksa;
}

__global__ void k_kvred(){
    int i = blockIdx.x*256 + threadIdx.x;   // 1024*256 = 262144
    if (i < 64*4096){
        float s = 0.f;
        int bh = i >> 12, e = i & 4095;
        for (int c=0;c<16;c++) s += g_kvp[((size_t)(c*64+bh))*4096 + e];
        g_kv[i] = s;
    }
    if (i < 64*64){
        float s = 0.f;
        int bh = i >> 6, d = i & 63;
        for (int c=0;c<16;c++) s += g_ksp[(c*64+bh)*64 + d];
        g_ks[i] = s;
    }
}

// ---------------- qf = (elu(rope(qh))+1) with z folded in ----------------
__global__ void k_qf(){
    int gw = blockIdx.x*8 + (threadIdx.x>>5);
    int lane = threadIdx.x & 31;
    if (gw >= MROWS*4) return;
    int row = gw >> 2, h = gw & 3;
    int n = row % NSEQ, b = row / NSEQ;
    const float* base = g_qkv + (size_t)row*768 + h*64;
    float x1 = base[2*lane], x2 = base[2*lane+1];
    float c = g_cos[n*32+lane], s = g_sin[n*32+lane];
    float q1 = elu1(x1*c - x2*s);
    float q2 = elu1(x1*s + x2*c);
    const float* ks = g_ks + (b*4+h)*64;
    float pd = q1*ks[2*lane] + q2*ks[2*lane+1];
    #pragma unroll
    for (int o=16;o;o>>=1) pd += __shfl_xor_sync(0xffffffffu, pd, o);
    float z = 1.f/(pd + 1e-6f);
    float* out = g_qf + (size_t)row*256 + h*64;
    out[2*lane]   = q1*z;
    out[2*lane+1] = q2*z;
}

// ---------------- cache write attention + update ----------------
__global__ void k_write(const float* __restrict__ Wwg, const float* __restrict__ bwg,
                        int l, int it, int pas){
    int b = blockIdx.x >> 4, k = blockIdx.x & 15;
    int t = threadIdx.x;     // 128
    __shared__ float sq[128], nc[128], sc[64], red[4];
    __shared__ float wg_s;
    float* crow = g_cache + ((size_t)(b*48 + l*16 + k))*DSLOT;
    sq[t] = crow[t];
    __syncthreads();
    if (t < 64){
        const float* wkp = g_wk + b*8192 + t*128;
        float s = 0.f;
        for (int d2=0; d2<128; d2++) s += sq[d2]*wkp[d2];
        sc[t] = s * INV_SQRT_DC;
    }
    __syncthreads();
    if (t == 0){
        float mx = sc[0];
        for (int m=1;m<64;m++) mx = fmaxf(mx, sc[m]);
        float su = 0.f;
        for (int m=0;m<64;m++){ float e = expf(sc[m]-mx); sc[m]=e; su+=e; }
        float inv = 1.f/su;
        for (int m=0;m<64;m++) sc[m] *= inv;
    }
    __syncthreads();
    float acc = 0.f;
    for (int m=0;m<64;m++) acc += sc[m]*g_wv[b*8192 + m*128 + t];
    nc[t] = acc;
    float pg = sq[t]*Wwg[l*256 + t] + acc*Wwg[l*256 + 128 + t];
    #pragma unroll
    for (int o=16;o;o>>=1) pg += __shfl_down_sync(0xffffffffu, pg, o);
    if ((t&31)==0) red[t>>5] = pg;
    __syncthreads();
    if (t==0) wg_s = sigm(red[0]+red[1]+red[2]+red[3] + bwg[l]);
    __syncthreads();
    float wg = wg_s;
    crow[t] = sq[t] + wg*nc[t];
    if (t == 0) crow[128] = wg;
    if (t < 4){
        crow[137+t] = (t==it)  ? 1.f : 0.f;
        crow[141+t] = (t==pas) ? 1.f : 0.f;
    }
}

// ---------------- feedback (pass > 0) ----------------
__global__ void k_fbprep(const float* __restrict__ pae){
    int row = blockIdx.x, t = threadIdx.x;
    int b = row/900, s2 = row%900;
    const float* lg = g_logits + row*16;
    float mx = lg[0]; int am = 0;
    #pragma unroll
    for (int v2=1; v2<16; v2++){ float x = lg[v2]; if (x > mx){ mx=x; am=v2; } }
    float tr = g_cur[((size_t)(b*NSEQ) + TSq + s2)*256 + t];
    float pe = pae[am*256 + t];
    g_fbin[(size_t)row*512 + t]       = tr;
    g_fbin[(size_t)row*512 + 256 + t] = pe;
}

__global__ void k_fbapply(const float* __restrict__ bfb){
    size_t i = (size_t)blockIdx.x*256 + threadIdx.x;
    int row = (int)(i>>8), t = (int)(i&255);
    float g = sigm(g_fbout[i] + bfb[t]);
    int b = row/900, s2 = row%900;
    float tr = g_fbin[(size_t)row*512+t];
    float pe = g_fbin[(size_t)row*512+256+t];
    g_cur[((size_t)(b*NSEQ) + TSq + s2)*256 + t] = tr + g*pe;
}

// ---------------- output logits ----------------
__global__ void k_logits(const float* __restrict__ Wout, const float* __restrict__ bout,
                         float* __restrict__ out){
    int t = threadIdx.x;
    int rl = t >> 4, v2 = t & 15;
    int row = blockIdx.x*16 + rl;
    int b = row/900, s2 = row%900;
    const float* hr = g_h + ((size_t)(b*NSEQ) + TSq + s2)*256;
    float a = bout[v2];
    for (int d2=0; d2<256; d2++) a += hr[d2]*Wout[d2*16 + v2];
    out[(size_t)row*16 + v2] = a;
}

// ---------------- host ----------------
static void gemm(const float* A, const float* B, float* C,
                 int M, int N, int K, int lda, int ldb, int ldc,
                 int batches, int bdiv, long sA1, long sA2, long sB1, long sB2,
                 long sC1, long sC2, int doAdd){
    dim3 g(N/64, (M+63)/64, batches);
    k_gemm<<<g,256>>>(A,B,C,M,N,K,lda,ldb,ldc,bdiv,sA1,sA2,sB1,sB2,sC1,sC2,doAdd);
}

extern "C" void kernel_launch(void* const* d_in, const int* in_sizes, int n_in,
                              void* d_out, int out_size){
    const int*   di   = (const int*)d_in[0];
    const int*   dou  = (const int*)d_in[1];
    const int*   ti   = (const int*)d_in[2];
    const float* tok  = (const float*)d_in[3];
    const float* seg  = (const float*)d_in[4];
    const float* se   = (const float*)d_in[5];
    const float* lid  = (const float*)d_in[6];
    const float* Wq   = (const float*)d_in[7];
    const float* Wkr  = (const float*)d_in[8];
    const float* Wvr  = (const float*)d_in[9];
    const float* Wg   = (const float*)d_in[10];
    const float* bg   = (const float*)d_in[11];
    const float* Wqkv = (const float*)d_in[12];
    const float* Wo   = (const float*)d_in[13];
    const float* Wwk  = (const float*)d_in[14];
    const float* Wwv  = (const float*)d_in[15];
    const float* Wwg  = (const float*)d_in[16];
    const float* bwg  = (const float*)d_in[17];
    const float* Wout = (const float*)d_in[18];
    const float* bout = (const float*)d_in[19];
    const float* pae  = (const float*)d_in[20];
    const float* Wfb  = (const float*)d_in[21];
    const float* bfb  = (const float*)d_in[22];

    float* gq;   cudaGetSymbolAddress((void**)&gq,   g_q);
    float* gh;   cudaGetSymbolAddress((void**)&gh,   g_h);
    float* gsc;  cudaGetSymbolAddress((void**)&gsc,  g_sc);
    float* gqf;  cudaGetSymbolAddress((void**)&gqf,  g_qf);
    float* gatt; cudaGetSymbolAddress((void**)&gatt, g_att);
    float* gqkv; cudaGetSymbolAddress((void**)&gqkv, g_qkv);
    float* gkc;  cudaGetSymbolAddress((void**)&gkc,  g_kc);
    float* gvc;  cudaGetSymbolAddress((void**)&gvc,  g_vc);
    float* gkv;  cudaGetSymbolAddress((void**)&gkv,  g_kv);
    float* gwk;  cudaGetSymbolAddress((void**)&gwk,  g_wk);
    float* gwv;  cudaGetSymbolAddress((void**)&gwv,  g_wv);
    float* gfbi; cudaGetSymbolAddress((void**)&gfbi, g_fbin);
    float* gfbo; cudaGetSymbolAddress((void**)&gfbo, g_fbout);
    float* glg;  cudaGetSymbolAddress((void**)&glg,  g_logits);

    k_rope<<<(NSEQ*32+255)/256,256>>>();
    k_embed<<<dim3(NSEQ,BBn),256>>>(di, dou, ti, tok, seg);
    k_cache_init<<<(BBn*48*DSLOT+255)/256,256>>>(se, lid);

    for (int pas=0; pas<2; pas++){
        if (pas > 0){
            k_fbprep<<<FBROWS,256>>>(pae);
            gemm(gfbi, Wfb, gfbo, FBROWS, 256, 512, 512, 256, 256,
                 1,1, 0,0, 0,0, 0,0, 0);
            k_fbapply<<<(FBROWS*256)/256,256>>>(bfb);
        }
        k_copy<<<(MROWS*DD/4)/256,256>>>();
        for (int l=0; l<LL; l++){
            for (int it=0; it<2; it++){
                // q = h @ Wq_read[l]
                gemm(gh, Wq + (size_t)l*256*128, gq, MROWS, 128, 256, 256, 128, 128,
                     1,1, 0,0, 0,0, 0,0, 0);
                // cache k^T, v
                k_cachekv<<<(BBn*20480+255)/256,256>>>(Wkr + (size_t)l*DSLOT*128,
                                                       Wvr + (size_t)l*DSLOT*256);
                // scores = q @ kT (batched over b)
                gemm(gq, gkc, gsc, NSEQ, 64, 128, 128, 64, 64,
                     BBn,1, (long)NSEQ*128,0, 8192,0, (long)NSEQ*64,0, 0);
                // softmax + rgate fold
                k_softrg<<<MROWS/8,256>>>(Wg, bg, l);
                // h += attn_scaled @ v
                gemm(gsc, gvc, gh, NSEQ, 256, 48, 64, 256, 256,
                     BBn,1, (long)NSEQ*64,0, 12288,0, (long)NSEQ*256,0, 1);
                // qkv = h @ Wqkv[l]
                gemm(gh, Wqkv + (size_t)l*256*768, gqkv, MROWS, 768, 256, 256, 768, 768,
                     1,1, 0,0, 0,0, 0,0, 0);
                // kv / ksum
                k_kvacc<<<dim3(16,64),256>>>();
                k_kvred<<<1024,256>>>();
                // qf with z folded
                k_qf<<<(MROWS*4)/8,256>>>();
                // att = qf @ kv (batched over b,h)
                gemm(gqf, gkv, gatt, NSEQ, 64, 64, 256, 64, 256,
                     64,4, (long)NSEQ*256,64, 4*4096,4096, (long)NSEQ*256,64, 0);
                // h += att @ Wo[l]
                gemm(gatt, Wo + (size_t)l*256*256, gh, MROWS, 256, 256, 256, 256, 256,
                     1,1, 0,0, 0,0, 0,0, 1);
                // write projections (last 64 tokens per batch)
                gemm(gh + (size_t)(NSEQ-64)*256, Wwk + (size_t)l*256*128, gwk,
                     64, 128, 256, 256, 128, 128,
                     BBn,1, (long)NSEQ*256,0, 0,0, 64*128,0, 0);
                gemm(gh + (size_t)(NSEQ-64)*256, Wwv + (size_t)l*256*128, gwv,
                     64, 128, 256, 256, 128, 128,
                     BBn,1, (long)NSEQ*256,0, 0,0, 64*128,0, 0);
                // cache write
                k_write<<<BBn*16,128>>>(Wwg, bwg, l, it, pas);
            }
        }
        if (pas == 0) k_logits<<<FBROWS/16,256>>>(Wout, bout, glg);
        else          k_logits<<<FBROWS/16,256>>>(Wout, bout, (float*)d_out);
    }
}

// round 3
// speedup vs baseline: 1.2920x; 1.2920x over previous
#include <cuda_runtime.h>
#include <cuda_bf16.h>
#include <cstdint>
#include <cstddef>

#define DD     256
#define LL     3
#define NSEQ   6300
#define TSq    5400
#define BBn    16
#define MROWS  (BBn*NSEQ)
#define FBROWS (BBn*900)
#define DSLOT  145
#define INV_SQRT_DC 0.08838834764831843f

// ---------------- scratch (device globals) ----------------
__device__ float g_cur [(size_t)MROWS*DD];
__device__ float g_h   [(size_t)MROWS*DD];
__device__ float g_q   [(size_t)MROWS*128];
__device__ float g_sc  [(size_t)MROWS*64];
__device__ float g_qf  [(size_t)MROWS*DD];
__device__ float g_att [(size_t)MROWS*DD];
__device__ float g_qkv [(size_t)MROWS*768];
__device__ float g_cache[BBn*48*DSLOT];
__device__ float g_kc  [BBn*128*64];
__device__ float g_vc  [BBn*48*256];
__device__ float g_kv  [64*4096];
__device__ float g_ks  [64*64];
__device__ float g_kvp [16*64*4096];
__device__ float g_ksp [16*64*64];
__device__ float g_wk  [BBn*64*128];
__device__ float g_wv  [BBn*64*128];
__device__ float g_cos [NSEQ*32];
__device__ float g_sin [NSEQ*32];
__device__ float g_logits[FBROWS*16];
__device__ float g_fbin [(size_t)FBROWS*512];
__device__ float g_fbout[(size_t)FBROWS*256];

__device__ __forceinline__ float sigm(float x){ return 1.f/(1.f+expf(-x)); }
__device__ __forceinline__ float elu1(float x){ return x>0.f ? x+1.f : expf(x); }

// ---------------- init ----------------
__global__ void k_rope(){
    int i = blockIdx.x*256 + threadIdx.x;
    if (i >= NSEQ*32) return;
    int n = i/32, j = i%32;
    float inv = 1.f/powf(10000.f, (float)(2*j)/64.f);
    float f = (float)n * inv;
    g_cos[i] = cosf(f);
    g_sin[i] = sinf(f);
}

__global__ void k_embed(const int* __restrict__ di, const int* __restrict__ dou,
                        const int* __restrict__ ti, const float* __restrict__ tok,
                        const float* __restrict__ seg){
    int n = blockIdx.x, b = blockIdx.y, t = threadIdx.x;
    int tk;
    if (n < TSq){
        int d = n/1800, rem = n%1800, w = rem/900, s = rem%900;
        tk = w ? dou[(b*3+d)*900+s] : di[(b*3+d)*900+s];
    } else {
        tk = ti[b*900 + (n-TSq)];
    }
    g_cur[((size_t)b*NSEQ+n)*DD + t] = tok[tk*DD+t] + seg[t];
}

__global__ void k_cache_init(const float* __restrict__ se, const float* __restrict__ lid){
    int i = blockIdx.x*256 + threadIdx.x;
    if (i >= BBn*48*DSLOT) return;
    int r2 = i % (48*DSLOT);
    int slot = r2 / DSLOT, c = r2 % DSLOT;
    float v = 0.f;
    if (c < 128)                  v = se[slot*128 + c];
    else if (c >= 129 && c < 137) v = lid[(slot/16)*8 + (c-129)];
    g_cache[i] = v;
}

__global__ void k_copy(){
    size_t i = (size_t)blockIdx.x*256 + threadIdx.x;
    ((float4*)g_h)[i] = ((const float4*)g_cur)[i];
}

// ---------------- split-bf16 helpers ----------------
__device__ __forceinline__ void split2(float x, uint16_t& h, uint16_t& l){
    __nv_bfloat16 bh = __float2bfloat16_rn(x);
    float r = x - __bfloat162float(bh);
    __nv_bfloat16 bl = __float2bfloat16_rn(r);
    h = *(uint16_t*)&bh;
    l = *(uint16_t*)&bl;
}

__device__ __forceinline__ void store4split(uint16_t* ph, uint16_t* pl, float4 v){
    uint16_t h0,l0,h1,l1,h2,l2,h3,l3;
    split2(v.x,h0,l0); split2(v.y,h1,l1); split2(v.z,h2,l2); split2(v.w,h3,l3);
    *(uint2*)ph = make_uint2((uint32_t)h0 | ((uint32_t)h1<<16),
                             (uint32_t)h2 | ((uint32_t)h3<<16));
    *(uint2*)pl = make_uint2((uint32_t)l0 | ((uint32_t)l1<<16),
                             (uint32_t)l2 | ((uint32_t)l3<<16));
}

__device__ __forceinline__ void mma16816(float* c, const uint32_t* a, const uint32_t* b){
    asm volatile(
      "mma.sync.aligned.m16n8k16.row.col.f32.bf16.bf16.f32 "
      "{%0,%1,%2,%3},{%4,%5,%6,%7},{%8,%9},{%0,%1,%2,%3};\n"
      : "+f"(c[0]),"+f"(c[1]),"+f"(c[2]),"+f"(c[3])
      : "r"(a[0]),"r"(a[1]),"r"(a[2]),"r"(a[3]), "r"(b[0]),"r"(b[1]));
}

// ---------------- tensor-core GEMM (split-bf16, fp32-accurate) ----------------
// C[M,N] (+)= A[M,K] @ B[K,N]; CTA tile 128x64, K-step 16, 256 thr.
// Requires: N % 64 == 0, K % 16 == 0, 16B-aligned pointers/ld.
// Batched: bz=blockIdx.z; b1=bz/bdiv, b2=bz%bdiv; strides sX1/sX2 (floats).
__global__ void __launch_bounds__(256) k_gemm_mma(
    const float* __restrict__ A, const float* __restrict__ B, float* __restrict__ C,
    int M, int N, int K, int lda, int ldb, int ldc,
    int bdiv, long sA1, long sA2, long sB1, long sB2, long sC1, long sC2, int doAdd)
{
    __shared__ __align__(16) uint16_t Ah[128][16];
    __shared__ __align__(16) uint16_t Al[128][16];
    __shared__ __align__(16) uint16_t Bh2[64][16];
    __shared__ __align__(16) uint16_t Bl2[64][16];

    int bz = blockIdx.z;
    int b1 = bz / bdiv, b2 = bz % bdiv;
    A += (size_t)b1*sA1 + (size_t)b2*sA2;
    B += (size_t)b1*sB1 + (size_t)b2*sB2;
    C += (size_t)b1*sC1 + (size_t)b2*sC2;

    const int t = threadIdx.x;
    const int wid = t>>5, lane = t&31;
    const int g = lane>>2, t4 = lane&3;
    const int wm = wid>>1, wn = wid&1;
    const int by = blockIdx.y;
    const int bxo = blockIdx.x*64;

    // A tile loads: two quads per thread (rows ar0 and ar0+64)
    const int ar0 = t>>2;
    const int ac0 = (t&3)<<2;
    const int gr0 = by*128 + ar0;
    // B tile load: one float4 per thread
    const int br = t>>4;
    const int bc = (t&15)<<2;

    float acc[2][4][4];
    #pragma unroll
    for (int i=0;i<2;i++)
        #pragma unroll
        for (int j=0;j<4;j++)
            #pragma unroll
            for (int q=0;q<4;q++) acc[i][j][q]=0.f;

    const int nk = K >> 4;
    float4 a0v, a1v, bv;

    // prologue: load k-tile 0
    {
        a0v = make_float4(0.f,0.f,0.f,0.f);
        a1v = make_float4(0.f,0.f,0.f,0.f);
        if (gr0     < M) a0v = *(const float4*)(A + (size_t)gr0*lda + ac0);
        if (gr0+64  < M) a1v = *(const float4*)(A + (size_t)(gr0+64)*lda + ac0);
        bv = *(const float4*)(B + (size_t)br*ldb + bxo + bc);
        store4split(&Ah[ar0][ac0],    &Al[ar0][ac0],    a0v);
        store4split(&Ah[ar0+64][ac0], &Al[ar0+64][ac0], a1v);
        const float* bp = &bv.x;
        #pragma unroll
        for (int j=0;j<4;j++){
            int n = bc+j;
            uint16_t h,l; split2(bp[j],h,l);
            int kk = br ^ (n&12);
            Bh2[n][kk] = h; Bl2[n][kk] = l;
        }
    }
    __syncthreads();

    for (int kt=0; kt<nk; kt++){
        // prefetch next k-tile into registers
        bool more = (kt+1 < nk);
        if (more){
            int k0 = (kt+1)<<4;
            a0v = make_float4(0.f,0.f,0.f,0.f);
            a1v = make_float4(0.f,0.f,0.f,0.f);
            if (gr0    < M) a0v = *(const float4*)(A + (size_t)gr0*lda + k0 + ac0);
            if (gr0+64 < M) a1v = *(const float4*)(A + (size_t)(gr0+64)*lda + k0 + ac0);
            bv = *(const float4*)(B + (size_t)(k0+br)*ldb + bxo + bc);
        }

        // compute from smem
        uint32_t afh[2][4], afl[2][4], bfh[4][2], bfl[4][2];
        #pragma unroll
        for (int mt=0; mt<2; mt++){
            int m = wm*32 + mt*16 + g;
            afh[mt][0] = *(const uint32_t*)&Ah[m  ][t4*2];
            afh[mt][1] = *(const uint32_t*)&Ah[m+8][t4*2];
            afh[mt][2] = *(const uint32_t*)&Ah[m  ][t4*2+8];
            afh[mt][3] = *(const uint32_t*)&Ah[m+8][t4*2+8];
            afl[mt][0] = *(const uint32_t*)&Al[m  ][t4*2];
            afl[mt][1] = *(const uint32_t*)&Al[m+8][t4*2];
            afl[mt][2] = *(const uint32_t*)&Al[m  ][t4*2+8];
            afl[mt][3] = *(const uint32_t*)&Al[m+8][t4*2+8];
        }
        #pragma unroll
        for (int nt=0; nt<4; nt++){
            int n = wn*32 + nt*8 + g;
            int kk0 = (t4*2)   ^ (n&12);
            int kk1 = (t4*2+8) ^ (n&12);
            bfh[nt][0] = *(const uint32_t*)&Bh2[n][kk0];
            bfh[nt][1] = *(const uint32_t*)&Bh2[n][kk1];
            bfl[nt][0] = *(const uint32_t*)&Bl2[n][kk0];
            bfl[nt][1] = *(const uint32_t*)&Bl2[n][kk1];
        }
        #pragma unroll
        for (int mt=0; mt<2; mt++){
            #pragma unroll
            for (int nt=0; nt<4; nt++){
                mma16816(acc[mt][nt], afh[mt], bfh[nt]);
                mma16816(acc[mt][nt], afh[mt], bfl[nt]);
                mma16816(acc[mt][nt], afl[mt], bfh[nt]);
            }
        }
        __syncthreads();

        if (more){
            store4split(&Ah[ar0][ac0],    &Al[ar0][ac0],    a0v);
            store4split(&Ah[ar0+64][ac0], &Al[ar0+64][ac0], a1v);
            const float* bp = &bv.x;
            #pragma unroll
            for (int j=0;j<4;j++){
                int n = bc+j;
                uint16_t h,l; split2(bp[j],h,l);
                int kk = br ^ (n&12);
                Bh2[n][kk] = h; Bl2[n][kk] = l;
            }
            __syncthreads();
        }
    }

    // epilogue
    #pragma unroll
    for (int mt=0; mt<2; mt++){
        #pragma unroll
        for (int nt=0; nt<4; nt++){
            int row = by*128 + wm*32 + mt*16 + g;
            int col = bxo + wn*32 + nt*8 + t4*2;
            if (row < M){
                float2* p = (float2*)(C + (size_t)row*ldc + col);
                float2 v = make_float2(acc[mt][nt][0], acc[mt][nt][1]);
                if (doAdd){ float2 c0 = *p; v.x += c0.x; v.y += c0.y; }
                *p = v;
            }
            if (row+8 < M){
                float2* p = (float2*)(C + (size_t)(row+8)*ldc + col);
                float2 v = make_float2(acc[mt][nt][2], acc[mt][nt][3]);
                if (doAdd){ float2 c0 = *p; v.x += c0.x; v.y += c0.y; }
                *p = v;
            }
        }
    }
}

// ---------------- cache k,v projections (k transposed + padded) ----------------
__global__ void k_cachekv(const float* __restrict__ Wk, const float* __restrict__ Wv){
    int idx = blockIdx.x*256 + threadIdx.x;
    if (idx >= BBn*20480) return;
    int b = idx / 20480, o = idx % 20480;
    const float* cb = g_cache + (size_t)b*48*DSLOT;
    if (o < 8192){
        int d = o >> 6, m = o & 63;
        float a = 0.f;
        if (m < 48){
            const float* row = cb + (size_t)m*DSLOT;
            for (int dd=0; dd<DSLOT; dd++) a += row[dd]*Wk[dd*128 + d];
        }
        g_kc[b*8192 + d*64 + m] = a;
    } else {
        int o2 = o - 8192;
        int m = o2 >> 8, j = o2 & 255;
        const float* row = cb + (size_t)m*DSLOT;
        float a = 0.f;
        for (int dd=0; dd<DSLOT; dd++) a += row[dd]*Wv[dd*256 + j];
        g_vc[b*12288 + o2] = a;
    }
}

// ---------------- softmax over 48 slots + fold rgate into weights ----------------
__global__ void k_softrg(const float* __restrict__ Wg, const float* __restrict__ bg, int l){
    int gw = blockIdx.x*8 + (threadIdx.x>>5);
    int lane = threadIdx.x & 31;
    if (gw >= MROWS) return;
    const float* hrow = g_h + (size_t)gw*256;
    const float* wg = Wg + l*256;
    float pg = 0.f;
    #pragma unroll
    for (int j=0;j<8;j++) pg += hrow[lane + 32*j]*wg[lane + 32*j];
    #pragma unroll
    for (int o=16;o;o>>=1) pg += __shfl_xor_sync(0xffffffffu, pg, o);
    float rgate = sigm(pg + bg[l]);
    float* scp = g_sc + (size_t)gw*64;
    float s0 = scp[lane]*INV_SQRT_DC;
    float s1 = (lane<16) ? scp[lane+32]*INV_SQRT_DC : -1e30f;
    float mx = fmaxf(s0, s1);
    #pragma unroll
    for (int o=16;o;o>>=1) mx = fmaxf(mx, __shfl_xor_sync(0xffffffffu, mx, o));
    float e0 = expf(s0-mx);
    float e1 = (lane<16) ? expf(s1-mx) : 0.f;
    float su = e0+e1;
    #pragma unroll
    for (int o=16;o;o>>=1) su += __shfl_xor_sync(0xffffffffu, su, o);
    float sc = rgate/su;
    scp[lane] = e0*sc;
    if (lane<16) scp[lane+32] = e1*sc;
}

// ---------------- linear attention: kv / ksum partials ----------------
__global__ void __launch_bounds__(256) k_kvacc(){
    int bh = blockIdx.y;
    int b = bh >> 2, h = bh & 3;
    int n0 = blockIdx.x*396;
    __shared__ float kf[4*64];
    __shared__ float vh[4*64];
    int t = threadIdx.x;
    int d = t >> 2, eb = (t & 3) << 4;
    float acc[16];
    #pragma unroll
    for (int j=0;j<16;j++) acc[j]=0.f;
    float ksa = 0.f;
    for (int nb=0; nb<396; nb+=4){
        int nbase = n0 + nb;
        if (t < 128){
            int sub = t>>5, i2 = t&31;
            int n = nbase + sub;
            float v1=0.f, v2=0.f;
            if (n < NSEQ){
                const float* bp = g_qkv + (size_t)(b*NSEQ+n)*768 + 256 + h*64;
                float x1=bp[2*i2], x2=bp[2*i2+1];
                float c=g_cos[n*32+i2], s=g_sin[n*32+i2];
                v1 = elu1(x1*c - x2*s);
                v2 = elu1(x1*s + x2*c);
            }
            kf[sub*64+2*i2]=v1; kf[sub*64+2*i2+1]=v2;
        } else {
            int t2 = t-128;
            #pragma unroll
            for (int q2=0;q2<2;q2++){
                int idx = t2 + q2*128;
                int sub = idx>>6, j = idx&63;
                int n = nbase + sub;
                vh[sub*64+j] = (n<NSEQ) ? g_qkv[(size_t)(b*NSEQ+n)*768 + 512 + h*64 + j] : 0.f;
            }
        }
        __syncthreads();
        #pragma unroll
        for (int sub=0; sub<4; sub++){
            float kd = kf[sub*64+d];
            ksa += kd;
            const float4* vp = (const float4*)&vh[sub*64+eb];
            #pragma unroll
            for (int q4=0;q4<4;q4++){
                float4 v4 = vp[q4];
                acc[q4*4+0]+=kd*v4.x; acc[q4*4+1]+=kd*v4.y;
                acc[q4*4+2]+=kd*v4.z; acc[q4*4+3]+=kd*v4.w;
            }
        }
        __syncthreads();
    }
    float* kvp = g_kvp + ((size_t)(blockIdx.x*64+bh))*4096 + d*64 + eb;
    #pragma unroll
    for (int j=0;j<16;j++) kvp[j] = acc[j];
    if ((t&3)==0) g_ksp[(blockIdx.x*64+bh)*64 + d] = ksa;
}

__global__ void k_kvred(){
    int i = blockIdx.x*256 + threadIdx.x;
    if (i < 64*4096){
        float s = 0.f;
        int bh = i >> 12, e = i & 4095;
        for (int c=0;c<16;c++) s += g_kvp[((size_t)(c*64+bh))*4096 + e];
        g_kv[i] = s;
    }
    if (i < 64*64){
        float s = 0.f;
        int bh = i >> 6, d = i & 63;
        for (int c=0;c<16;c++) s += g_ksp[(c*64+bh)*64 + d];
        g_ks[i] = s;
    }
}

// ---------------- qf = (elu(rope(qh))+1) with z folded in ----------------
__global__ void k_qf(){
    int gw = blockIdx.x*8 + (threadIdx.x>>5);
    int lane = threadIdx.x & 31;
    if (gw >= MROWS*4) return;
    int row = gw >> 2, h = gw & 3;
    int n = row % NSEQ, b = row / NSEQ;
    const float* base = g_qkv + (size_t)row*768 + h*64;
    float x1 = base[2*lane], x2 = base[2*lane+1];
    float c = g_cos[n*32+lane], s = g_sin[n*32+lane];
    float q1 = elu1(x1*c - x2*s);
    float q2 = elu1(x1*s + x2*c);
    const float* ks = g_ks + (b*4+h)*64;
    float pd = q1*ks[2*lane] + q2*ks[2*lane+1];
    #pragma unroll
    for (int o=16;o;o>>=1) pd += __shfl_xor_sync(0xffffffffu, pd, o);
    float z = 1.f/(pd + 1e-6f);
    float* out = g_qf + (size_t)row*256 + h*64;
    out[2*lane]   = q1*z;
    out[2*lane+1] = q2*z;
}

// ---------------- cache write attention + update ----------------
__global__ void k_write(const float* __restrict__ Wwg, const float* __restrict__ bwg,
                        int l, int it, int pas){
    int b = blockIdx.x >> 4, k = blockIdx.x & 15;
    int t = threadIdx.x;
    __shared__ float sq[128], nc[128], sc[64], red[4];
    __shared__ float wg_s;
    float* crow = g_cache + ((size_t)(b*48 + l*16 + k))*DSLOT;
    sq[t] = crow[t];
    __syncthreads();
    if (t < 64){
        const float* wkp = g_wk + b*8192 + t*128;
        float s = 0.f;
        for (int d2=0; d2<128; d2++) s += sq[d2]*wkp[d2];
        sc[t] = s * INV_SQRT_DC;
    }
    __syncthreads();
    if (t == 0){
        float mx = sc[0];
        for (int m=1;m<64;m++) mx = fmaxf(mx, sc[m]);
        float su = 0.f;
        for (int m=0;m<64;m++){ float e = expf(sc[m]-mx); sc[m]=e; su+=e; }
        float inv = 1.f/su;
        for (int m=0;m<64;m++) sc[m] *= inv;
    }
    __syncthreads();
    float acc = 0.f;
    for (int m=0;m<64;m++) acc += sc[m]*g_wv[b*8192 + m*128 + t];
    nc[t] = acc;
    float pg = sq[t]*Wwg[l*256 + t] + acc*Wwg[l*256 + 128 + t];
    #pragma unroll
    for (int o=16;o;o>>=1) pg += __shfl_down_sync(0xffffffffu, pg, o);
    if ((t&31)==0) red[t>>5] = pg;
    __syncthreads();
    if (t==0) wg_s = sigm(red[0]+red[1]+red[2]+red[3] + bwg[l]);
    __syncthreads();
    float wg = wg_s;
    crow[t] = sq[t] + wg*nc[t];
    if (t == 0) crow[128] = wg;
    if (t < 4){
        crow[137+t] = (t==it)  ? 1.f : 0.f;
        crow[141+t] = (t==pas) ? 1.f : 0.f;
    }
}

// ---------------- feedback (pass > 0) ----------------
__global__ void k_fbprep(const float* __restrict__ pae){
    int row = blockIdx.x, t = threadIdx.x;
    int b = row/900, s2 = row%900;
    const float* lg = g_logits + row*16;
    float mx = lg[0]; int am = 0;
    #pragma unroll
    for (int v2=1; v2<16; v2++){ float x = lg[v2]; if (x > mx){ mx=x; am=v2; } }
    float tr = g_cur[((size_t)(b*NSEQ) + TSq + s2)*256 + t];
    float pe = pae[am*256 + t];
    g_fbin[(size_t)row*512 + t]       = tr;
    g_fbin[(size_t)row*512 + 256 + t] = pe;
}

__global__ void k_fbapply(const float* __restrict__ bfb){
    size_t i = (size_t)blockIdx.x*256 + threadIdx.x;
    int row = (int)(i>>8), t = (int)(i&255);
    float g = sigm(g_fbout[i] + bfb[t]);
    int b = row/900, s2 = row%900;
    float tr = g_fbin[(size_t)row*512+t];
    float pe = g_fbin[(size_t)row*512+256+t];
    g_cur[((size_t)(b*NSEQ) + TSq + s2)*256 + t] = tr + g*pe;
}

// ---------------- output logits ----------------
__global__ void k_logits(const float* __restrict__ Wout, const float* __restrict__ bout,
                         float* __restrict__ out){
    int t = threadIdx.x;
    int rl = t >> 4, v2 = t & 15;
    int row = blockIdx.x*16 + rl;
    int b = row/900, s2 = row%900;
    const float* hr = g_h + ((size_t)(b*NSEQ) + TSq + s2)*256;
    float a = bout[v2];
    for (int d2=0; d2<256; d2++) a += hr[d2]*Wout[d2*16 + v2];
    out[(size_t)row*16 + v2] = a;
}

// ---------------- host ----------------
static void gemm(const float* A, const float* B, float* C,
                 int M, int N, int K, int lda, int ldb, int ldc,
                 int batches, int bdiv, long sA1, long sA2, long sB1, long sB2,
                 long sC1, long sC2, int doAdd){
    dim3 g(N/64, (M+127)/128, batches);
    k_gemm_mma<<<g,256>>>(A,B,C,M,N,K,lda,ldb,ldc,bdiv,sA1,sA2,sB1,sB2,sC1,sC2,doAdd);
}

extern "C" void kernel_launch(void* const* d_in, const int* in_sizes, int n_in,
                              void* d_out, int out_size){
    const int*   di   = (const int*)d_in[0];
    const int*   dou  = (const int*)d_in[1];
    const int*   ti   = (const int*)d_in[2];
    const float* tok  = (const float*)d_in[3];
    const float* seg  = (const float*)d_in[4];
    const float* se   = (const float*)d_in[5];
    const float* lid  = (const float*)d_in[6];
    const float* Wq   = (const float*)d_in[7];
    const float* Wkr  = (const float*)d_in[8];
    const float* Wvr  = (const float*)d_in[9];
    const float* Wg   = (const float*)d_in[10];
    const float* bg   = (const float*)d_in[11];
    const float* Wqkv = (const float*)d_in[12];
    const float* Wo   = (const float*)d_in[13];
    const float* Wwk  = (const float*)d_in[14];
    const float* Wwv  = (const float*)d_in[15];
    const float* Wwg  = (const float*)d_in[16];
    const float* bwg  = (const float*)d_in[17];
    const float* Wout = (const float*)d_in[18];
    const float* bout = (const float*)d_in[19];
    const float* pae  = (const float*)d_in[20];
    const float* Wfb  = (const float*)d_in[21];
    const float* bfb  = (const float*)d_in[22];

    float* gq;   cudaGetSymbolAddress((void**)&gq,   g_q);
    float* gh;   cudaGetSymbolAddress((void**)&gh,   g_h);
    float* gsc;  cudaGetSymbolAddress((void**)&gsc,  g_sc);
    float* gqf;  cudaGetSymbolAddress((void**)&gqf,  g_qf);
    float* gatt; cudaGetSymbolAddress((void**)&gatt, g_att);
    float* gqkv; cudaGetSymbolAddress((void**)&gqkv, g_qkv);
    float* gkc;  cudaGetSymbolAddress((void**)&gkc,  g_kc);
    float* gvc;  cudaGetSymbolAddress((void**)&gvc,  g_vc);
    float* gkv;  cudaGetSymbolAddress((void**)&gkv,  g_kv);
    float* gwk;  cudaGetSymbolAddress((void**)&gwk,  g_wk);
    float* gwv;  cudaGetSymbolAddress((void**)&gwv,  g_wv);
    float* gfbi; cudaGetSymbolAddress((void**)&gfbi, g_fbin);
    float* gfbo; cudaGetSymbolAddress((void**)&gfbo, g_fbout);
    float* glg;  cudaGetSymbolAddress((void**)&glg,  g_logits);

    k_rope<<<(NSEQ*32+255)/256,256>>>();
    k_embed<<<dim3(NSEQ,BBn),256>>>(di, dou, ti, tok, seg);
    k_cache_init<<<(BBn*48*DSLOT+255)/256,256>>>(se, lid);

    for (int pas=0; pas<2; pas++){
        if (pas > 0){
            k_fbprep<<<FBROWS,256>>>(pae);
            gemm(gfbi, Wfb, gfbo, FBROWS, 256, 512, 512, 256, 256,
                 1,1, 0,0, 0,0, 0,0, 0);
            k_fbapply<<<(FBROWS*256)/256,256>>>(bfb);
        }
        k_copy<<<(MROWS*DD/4)/256,256>>>();
        for (int l=0; l<LL; l++){
            for (int it=0; it<2; it++){
                gemm(gh, Wq + (size_t)l*256*128, gq, MROWS, 128, 256, 256, 128, 128,
                     1,1, 0,0, 0,0, 0,0, 0);
                k_cachekv<<<(BBn*20480+255)/256,256>>>(Wkr + (size_t)l*DSLOT*128,
                                                       Wvr + (size_t)l*DSLOT*256);
                gemm(gq, gkc, gsc, NSEQ, 64, 128, 128, 64, 64,
                     BBn,1, (long)NSEQ*128,0, 8192,0, (long)NSEQ*64,0, 0);
                k_softrg<<<MROWS/8,256>>>(Wg, bg, l);
                gemm(gsc, gvc, gh, NSEQ, 256, 48, 64, 256, 256,
                     BBn,1, (long)NSEQ*64,0, 12288,0, (long)NSEQ*256,0, 1);
                gemm(gh, Wqkv + (size_t)l*256*768, gqkv, MROWS, 768, 256, 256, 768, 768,
                     1,1, 0,0, 0,0, 0,0, 0);
                k_kvacc<<<dim3(16,64),256>>>();
                k_kvred<<<1024,256>>>();
                k_qf<<<(MROWS*4)/8,256>>>();
                gemm(gqf, gkv, gatt, NSEQ, 64, 64, 256, 64, 256,
                     64,4, (long)NSEQ*256,64, 4*4096,4096, (long)NSEQ*256,64, 0);
                gemm(gatt, Wo + (size_t)l*256*256, gh, MROWS, 256, 256, 256, 256, 256,
                     1,1, 0,0, 0,0, 0,0, 1);
                gemm(gh + (size_t)(NSEQ-64)*256, Wwk + (size_t)l*256*128, gwk,
                     64, 128, 256, 256, 128, 128,
                     BBn,1, (long)NSEQ*256,0, 0,0, 64*128,0, 0);
                gemm(gh + (size_t)(NSEQ-64)*256, Wwv + (size_t)l*256*128, gwv,
                     64, 128, 256, 256, 128, 128,
                     BBn,1, (long)NSEQ*256,0, 0,0, 64*128,0, 0);
                k_write<<<BBn*16,128>>>(Wwg, bwg, l, it, pas);
            }
        }
        if (pas == 0) k_logits<<<FBROWS/16,256>>>(Wout, bout, glg);
        else          k_logits<<<FBROWS/16,256>>>(Wout, bout, (float*)d_out);
    }
}